// round 4
// baseline (speedup 1.0000x reference)
#include <cuda_runtime.h>
#include <cuda_fp16.h>

#define NA 16       // agents
#define ND 256      // action dim (K of the GEMM)
#define NN 64       // K_kernels * NA = output cols (N of the GEMM)
#define MT 128      // rows per CTA
#define NTHREADS 256

// fp16 copy of si_W, prepared once per launch by prep_kernel (row n = k*16+a, col d)
__device__ __half g_Wh[NN * ND];

__device__ __forceinline__ unsigned pack_h2(float a, float b) {
    __half2 h = __floats2half2_rn(a, b);
    return *reinterpret_cast<unsigned*>(&h);
}

// ---------------------------------------------------------------------------
// Prep: convert si_W -> fp16, write attend_mag_regs + head_entropies tail.
// ---------------------------------------------------------------------------
__global__ void prep_kernel(const float* __restrict__ siW,
                            const float* __restrict__ sel,
                            const float* __restrict__ keys,
                            float* __restrict__ out,
                            int Btot, int out_size)
{
    int i = blockIdx.x * blockDim.x + threadIdx.x;
    if (i < NN * ND) g_Wh[i] = __float2half_rn(siW[i]);

    if (blockIdx.x == 0 && threadIdx.x == 0 && out_size >= Btot + 5) {
        float ssq = 0.f;
        for (int h = 0; h < 4; ++h) {
            float d = 0.f;
            for (int e = 0; e < 64; ++e) d = fmaf(sel[h * 64 + e], keys[h * 64 + e], d);
            ssq += d * d;
        }
        out[Btot] = 0.001f * ssq;                 // attend_mag_regs
        // softmax of identical logits is exactly 1/16 in fp32
        float aw = 0.0625f;
        float ent = -16.0f * (logf(aw + 1e-8f) * aw);
        for (int h = 0; h < 4; ++h) out[Btot + 1 + h] = ent;  // head_entropies
    }
}

// ---------------------------------------------------------------------------
// Main: GEMM (M=Btot, K=256, N=64) in fp16 mma.sync + fused epilogue.
//   A (actions) : global fp32 -> registers (converted to fp16), no smem stage
//   B (si_W)    : g_Wh -> smem, XOR-swizzled, ldmatrix
//   epilogue    : sigmoid, kern-weighting, adv_q dot, quad reduction
// ---------------------------------------------------------------------------
__global__ void __launch_bounds__(NTHREADS)
mixer_kernel(const float* __restrict__ aq,
             const float* __restrict__ acts,
             const float* __restrict__ mq,
             const float* __restrict__ Vp,
             const float* __restrict__ si_keys,
             const float* __restrict__ si_agents,
             const float* __restrict__ si_b,
             float* __restrict__ out,
             int Btot)
{
    __shared__ __half sB[NN * ND];   // 32 KB
    __shared__ float  sKern[NN];
    __shared__ float  sBias[NN];

    const int tid = threadIdx.x;

    // kern[n] = (|si_keys[k]| + 1e-10) * sigmoid(si_agents[k][a]);  bias[n] = si_b
    if (tid < NN) {
        int k = tid >> 4;
        float sg = 1.0f / (1.0f + __expf(-si_agents[tid]));
        sKern[tid] = (fabsf(si_keys[k]) + 1e-10f) * sg;
        sBias[tid] = si_b[tid];
    }

    // stage B: 64 rows x 256 halves, 16B segments, seg' = seg ^ (row&7) swizzle
#pragma unroll
    for (int it = 0; it < 8; ++it) {
        int s = it * NTHREADS + tid;
        int r = s >> 5, c8 = s & 31;
        uint4 v = *reinterpret_cast<const uint4*>(g_Wh + r * ND + c8 * 8);
        *reinterpret_cast<uint4*>(sB + r * ND + ((c8 ^ (r & 7)) << 3)) = v;
    }
    __syncthreads();

    const int w = tid >> 5, l = tid & 31;
    const int quad = l >> 2, qid = l & 3;
    const int l7 = l & 7, t8 = l >> 3;
    const long rowBase = (long)blockIdx.x * MT + w * 16;

    long r0 = rowBase + quad;
    long r1 = r0 + 8;
    long r0c = (r0 < Btot) ? r0 : (long)(Btot - 1);
    long r1c = (r1 < Btot) ? r1 : (long)(Btot - 1);
    const float* arow0 = acts + r0c * ND;
    const float* arow1 = acts + r1c * ND;
    const int cA = qid * 2;

    // B ldmatrix lane geometry (x4: two n-tiles per issue)
    const int rowB_off = (t8 >> 1) * 8 + l7;
    const int s0B = t8 & 1;
    const unsigned sBaddr = (unsigned)__cvta_generic_to_shared(sB);

    float acc[8][4];
#pragma unroll
    for (int i = 0; i < 8; ++i)
#pragma unroll
        for (int j = 0; j < 4; ++j) acc[i][j] = 0.f;

#pragma unroll 4
    for (int kk = 0; kk < 16; ++kk) {
        const int col = kk * 16 + cA;
        // A fragment straight from global (fp32 -> fp16 in regs)
        float2 f00 = *reinterpret_cast<const float2*>(arow0 + col);
        float2 f01 = *reinterpret_cast<const float2*>(arow0 + col + 8);
        float2 f10 = *reinterpret_cast<const float2*>(arow1 + col);
        float2 f11 = *reinterpret_cast<const float2*>(arow1 + col + 8);
        unsigned a0 = pack_h2(f00.x, f00.y);
        unsigned a1 = pack_h2(f10.x, f10.y);
        unsigned a2 = pack_h2(f01.x, f01.y);
        unsigned a3 = pack_h2(f11.x, f11.y);
#pragma unroll
        for (int p = 0; p < 4; ++p) {
            unsigned addrB = sBaddr
                           + (unsigned)((p * 16 + rowB_off) * (ND * 2))
                           + (unsigned)(((kk * 2 + s0B) ^ l7) << 4);
            unsigned b0, b1, b2, b3;
            asm volatile("ldmatrix.sync.aligned.m8n8.x4.shared.b16 {%0,%1,%2,%3}, [%4];\n"
                         : "=r"(b0), "=r"(b1), "=r"(b2), "=r"(b3) : "r"(addrB));
            asm volatile("mma.sync.aligned.m16n8k16.row.col.f32.f16.f16.f32 "
                         "{%0,%1,%2,%3}, {%4,%5,%6,%7}, {%8,%9}, {%0,%1,%2,%3};\n"
                         : "+f"(acc[2*p][0]), "+f"(acc[2*p][1]),
                           "+f"(acc[2*p][2]), "+f"(acc[2*p][3])
                         : "r"(a0), "r"(a1), "r"(a2), "r"(a3), "r"(b0), "r"(b1));
            asm volatile("mma.sync.aligned.m16n8k16.row.col.f32.f16.f16.f32 "
                         "{%0,%1,%2,%3}, {%4,%5,%6,%7}, {%8,%9}, {%0,%1,%2,%3};\n"
                         : "+f"(acc[2*p+1][0]), "+f"(acc[2*p+1][1]),
                           "+f"(acc[2*p+1][2]), "+f"(acc[2*p+1][3])
                         : "r"(a0), "r"(a1), "r"(a2), "r"(a3), "r"(b2), "r"(b3));
        }
    }

    // Epilogue. acc[nt][h*2+j] = logit for row (r0 + h*8), col n = nt*8 + cA + j.
    // a = n & 15 = (cA+j) + 8*(nt&1);  k = n >> 4 = nt >> 1.
    const float v = Vp[0] * 0.0625f;   // V/A (cancels in adv_q, kept for exactness)
    float partial[2] = {0.f, 0.f};
#pragma unroll
    for (int h = 0; h < 2; ++h) {
        long gr = (h == 0) ? r0c : r1c;
        const float* aqr = aq + gr * NA;
        const float* mqr = mq + gr * NA;
#pragma unroll
        for (int j = 0; j < 2; ++j) {
#pragma unroll
            for (int pp = 0; pp < 2; ++pp) {
                float s = 0.f;
#pragma unroll
                for (int q = 0; q < 4; ++q) {
                    int nt = 2 * q + pp;
                    int n = nt * 8 + cA + j;
                    float x = acc[nt][h * 2 + j] + sBias[n];
                    x = 1.0f / (1.0f + __expf(-x));
                    s = fmaf(x, sKern[n], s);
                }
                int a = cA + j + 8 * pp;
                float advq = fmaf(0.25f, aqr[a], v) - fmaf(0.25f, mqr[a], v);
                partial[h] += advq * (s - 1.0f);
            }
        }
    }
    // quad (4 lanes) hold disjoint a-subsets of the same rows -> butterfly sum
    partial[0] += __shfl_xor_sync(0xffffffffu, partial[0], 1);
    partial[0] += __shfl_xor_sync(0xffffffffu, partial[0], 2);
    partial[1] += __shfl_xor_sync(0xffffffffu, partial[1], 1);
    partial[1] += __shfl_xor_sync(0xffffffffu, partial[1], 2);
    if (qid == 0) {
        if (r0 < Btot) out[r0] = partial[0];
        if (r1 < Btot) out[r1] = partial[1];
    }
}

// ---------------------------------------------------------------------------
extern "C" void kernel_launch(void* const* d_in, const int* in_sizes, int n_in,
                              void* d_out, int out_size)
{
    const float* agent_qs  = (const float*)d_in[0];
    const float* actions   = (const float*)d_in[1];
    const float* max_q_i   = (const float*)d_in[2];
    const float* selectors = (const float*)d_in[3];
    const float* keys      = (const float*)d_in[4];
    const float* V         = (const float*)d_in[5];
    const float* si_keys   = (const float*)d_in[6];
    const float* si_agents = (const float*)d_in[7];
    const float* si_W      = (const float*)d_in[8];
    const float* si_b      = (const float*)d_in[9];
    float* out = (float*)d_out;

    int Btot = in_sizes[0] / NA;   // B0*T

    prep_kernel<<<64, 256>>>(si_W, selectors, keys, out, Btot, out_size);

    int grid = (Btot + MT - 1) / MT;
    mixer_kernel<<<grid, NTHREADS>>>(agent_qs, actions, max_q_i, V,
                                     si_keys, si_agents, si_b, out, Btot);
}

// round 5
// speedup vs baseline: 1.1118x; 1.1118x over previous
#include <cuda_runtime.h>
#include <cuda_fp16.h>

#define NA 16       // agents
#define ND 256      // action dim (K of the GEMM)
#define NN 64       // K_kernels * NA = output cols (N of the GEMM)
#define MT 128      // rows per CTA
#define NTHREADS 256

// fp16 copy of si_W with K-permuted columns (see phys_col), row n = k*16+a
__device__ __half g_Wh[NN * ND];

__device__ __forceinline__ unsigned pack_h2(float a, float b) {
    __half2 h = __floats2half2_rn(a, b);
    return *reinterpret_cast<unsigned*>(&h);
}

// Within each 16-wide K block: logical fragment col l -> physical col.
// logical {2q,2q+1}   -> phys {4q,4q+1}
// logical {2q+8,2q+9} -> phys {4q+2,4q+3}
__device__ __host__ __forceinline__ int phys_col(int l) {
    if (l < 8) return 4 * (l >> 1) + (l & 1);
    int lm = l - 8;
    return 4 * (lm >> 1) + 2 + (lm & 1);
}

// ---------------------------------------------------------------------------
// Prep: convert si_W -> fp16 with K-permutation, write scalar tail outputs.
// ---------------------------------------------------------------------------
__global__ void prep_kernel(const float* __restrict__ siW,
                            const float* __restrict__ sel,
                            const float* __restrict__ keys,
                            float* __restrict__ out,
                            int Btot, int out_size)
{
    int i = blockIdx.x * blockDim.x + threadIdx.x;
    if (i < NN * ND) {
        int n = i >> 8, col = i & 255;
        int kk = col >> 4, l = col & 15;
        g_Wh[i] = __float2half_rn(siW[n * ND + kk * 16 + phys_col(l)]);
    }

    if (blockIdx.x == 0 && threadIdx.x == 0 && out_size >= Btot + 5) {
        float ssq = 0.f;
        for (int h = 0; h < 4; ++h) {
            float d = 0.f;
            for (int e = 0; e < 64; ++e) d = fmaf(sel[h * 64 + e], keys[h * 64 + e], d);
            ssq += d * d;
        }
        out[Btot] = 0.001f * ssq;                 // attend_mag_regs
        float aw = 0.0625f;                        // softmax of equal logits
        float ent = -16.0f * (logf(aw + 1e-8f) * aw);
        for (int h = 0; h < 4; ++h) out[Btot + 1 + h] = ent;  // head_entropies
    }
}

// ---------------------------------------------------------------------------
// Main: GEMM (M=Btot, K=256, N=64) fp16 mma.sync + fused epilogue.
//   A : one LDG.128 per row per k-step (K-permuted fragment), streaming (.cs)
//   B : g_Wh -> smem, XOR-swizzled, ldmatrix
// ---------------------------------------------------------------------------
__global__ void __launch_bounds__(NTHREADS)
mixer_kernel(const float* __restrict__ aq,
             const float* __restrict__ acts,
             const float* __restrict__ mq,
             const float* __restrict__ Vp,
             const float* __restrict__ si_keys,
             const float* __restrict__ si_agents,
             const float* __restrict__ si_b,
             float* __restrict__ out,
             int Btot)
{
    __shared__ __half sB[NN * ND];   // 32 KB
    __shared__ float  sKern[NN];
    __shared__ float  sBias[NN];

    const int tid = threadIdx.x;

    // kern[n] = (|si_keys[k]|+1e-10) * sigmoid(si_agents[k][a]); bias[n] = si_b
    if (tid < NN) {
        int k = tid >> 4;
        float sg = 1.0f / (1.0f + __expf(-si_agents[tid]));
        sKern[tid] = (fabsf(si_keys[k]) + 1e-10f) * sg;
        sBias[tid] = si_b[tid];
    }

    // stage B: 64 rows x 256 halves, 16B segments, seg' = seg ^ (row&7) swizzle
#pragma unroll
    for (int it = 0; it < 8; ++it) {
        int s = it * NTHREADS + tid;
        int r = s >> 5, c8 = s & 31;
        uint4 v = *reinterpret_cast<const uint4*>(g_Wh + r * ND + c8 * 8);
        *reinterpret_cast<uint4*>(sB + r * ND + ((c8 ^ (r & 7)) << 3)) = v;
    }
    __syncthreads();

    const int w = tid >> 5, l = tid & 31;
    const int quad = l >> 2, qid = l & 3;
    const int l7 = l & 7, t8 = l >> 3;
    const long rowBase = (long)blockIdx.x * MT + w * 16;

    long r0 = rowBase + quad;
    long r1 = r0 + 8;
    long r0c = (r0 < Btot) ? r0 : (long)(Btot - 1);
    long r1c = (r1 < Btot) ? r1 : (long)(Btot - 1);
    const float4* arow0 = reinterpret_cast<const float4*>(acts + r0c * ND) + qid;
    const float4* arow1 = reinterpret_cast<const float4*>(acts + r1c * ND) + qid;
    const int cA = qid * 2;   // logical fragment columns within epilogue mapping

    // B ldmatrix lane geometry (x4: two n-tiles per issue)
    const int rowB_off = (t8 >> 1) * 8 + l7;
    const int s0B = t8 & 1;
    const unsigned sBaddr = (unsigned)__cvta_generic_to_shared(sB);

    float acc[8][4];
#pragma unroll
    for (int i = 0; i < 8; ++i)
#pragma unroll
        for (int j = 0; j < 4; ++j) acc[i][j] = 0.f;

#pragma unroll 4
    for (int kk = 0; kk < 16; ++kk) {
        // A fragment: single LDG.128 per row, streaming hint (no reuse)
        float4 f0 = __ldcs(arow0 + kk * 4);
        float4 f1 = __ldcs(arow1 + kk * 4);
        unsigned a0 = pack_h2(f0.x, f0.y);   // logical cols 2q,2q+1   (row r0)
        unsigned a1 = pack_h2(f1.x, f1.y);   // row r1
        unsigned a2 = pack_h2(f0.z, f0.w);   // logical cols 2q+8,2q+9 (row r0)
        unsigned a3 = pack_h2(f1.z, f1.w);   // row r1
#pragma unroll
        for (int p = 0; p < 4; ++p) {
            unsigned addrB = sBaddr
                           + (unsigned)((p * 16 + rowB_off) * (ND * 2))
                           + (unsigned)(((kk * 2 + s0B) ^ l7) << 4);
            unsigned b0, b1, b2, b3;
            asm volatile("ldmatrix.sync.aligned.m8n8.x4.shared.b16 {%0,%1,%2,%3}, [%4];\n"
                         : "=r"(b0), "=r"(b1), "=r"(b2), "=r"(b3) : "r"(addrB));
            asm volatile("mma.sync.aligned.m16n8k16.row.col.f32.f16.f16.f32 "
                         "{%0,%1,%2,%3}, {%4,%5,%6,%7}, {%8,%9}, {%0,%1,%2,%3};\n"
                         : "+f"(acc[2*p][0]), "+f"(acc[2*p][1]),
                           "+f"(acc[2*p][2]), "+f"(acc[2*p][3])
                         : "r"(a0), "r"(a1), "r"(a2), "r"(a3), "r"(b0), "r"(b1));
            asm volatile("mma.sync.aligned.m16n8k16.row.col.f32.f16.f16.f32 "
                         "{%0,%1,%2,%3}, {%4,%5,%6,%7}, {%8,%9}, {%0,%1,%2,%3};\n"
                         : "+f"(acc[2*p+1][0]), "+f"(acc[2*p+1][1]),
                           "+f"(acc[2*p+1][2]), "+f"(acc[2*p+1][3])
                         : "r"(a0), "r"(a1), "r"(a2), "r"(a3), "r"(b2), "r"(b3));
        }
    }

    // Epilogue. acc[nt][h*2+j] = logit for row (r0 + h*8), col n = nt*8 + cA + j.
    const float v = Vp[0] * 0.0625f;   // V/A (cancels in adv_q, kept for exactness)
    float partial[2] = {0.f, 0.f};
#pragma unroll
    for (int h = 0; h < 2; ++h) {
        long gr = (h == 0) ? r0c : r1c;
        const float* aqr = aq + gr * NA;
        const float* mqr = mq + gr * NA;
#pragma unroll
        for (int j = 0; j < 2; ++j) {
#pragma unroll
            for (int pp = 0; pp < 2; ++pp) {
                float s = 0.f;
#pragma unroll
                for (int q = 0; q < 4; ++q) {
                    int nt = 2 * q + pp;
                    int n = nt * 8 + cA + j;
                    float x = acc[nt][h * 2 + j] + sBias[n];
                    x = 1.0f / (1.0f + __expf(-x));
                    s = fmaf(x, sKern[n], s);
                }
                int a = cA + j + 8 * pp;
                float advq = fmaf(0.25f, __ldcs(aqr + a), v)
                           - fmaf(0.25f, __ldcs(mqr + a), v);
                partial[h] += advq * (s - 1.0f);
            }
        }
    }
    // quad (4 lanes) hold disjoint a-subsets of the same rows -> butterfly sum
    partial[0] += __shfl_xor_sync(0xffffffffu, partial[0], 1);
    partial[0] += __shfl_xor_sync(0xffffffffu, partial[0], 2);
    partial[1] += __shfl_xor_sync(0xffffffffu, partial[1], 1);
    partial[1] += __shfl_xor_sync(0xffffffffu, partial[1], 2);
    if (qid == 0) {
        if (r0 < Btot) out[r0] = partial[0];
        if (r1 < Btot) out[r1] = partial[1];
    }
}

// ---------------------------------------------------------------------------
extern "C" void kernel_launch(void* const* d_in, const int* in_sizes, int n_in,
                              void* d_out, int out_size)
{
    const float* agent_qs  = (const float*)d_in[0];
    const float* actions   = (const float*)d_in[1];
    const float* max_q_i   = (const float*)d_in[2];
    const float* selectors = (const float*)d_in[3];
    const float* keys      = (const float*)d_in[4];
    const float* V         = (const float*)d_in[5];
    const float* si_keys   = (const float*)d_in[6];
    const float* si_agents = (const float*)d_in[7];
    const float* si_W      = (const float*)d_in[8];
    const float* si_b      = (const float*)d_in[9];
    float* out = (float*)d_out;

    int Btot = in_sizes[0] / NA;   // B0*T

    prep_kernel<<<64, 256>>>(si_W, selectors, keys, out, Btot, out_size);

    int grid = (Btot + MT - 1) / MT;
    mixer_kernel<<<grid, NTHREADS>>>(agent_qs, actions, max_q_i, V,
                                     si_keys, si_agents, si_b, out, Btot);
}

// round 6
// speedup vs baseline: 1.1557x; 1.0394x over previous
#include <cuda_runtime.h>
#include <cuda_fp16.h>

#define NA 16       // agents
#define ND 256      // action dim (K of the GEMM)
#define NN 64       // K_kernels * NA = output cols (N of the GEMM)
#define MT 128      // rows per CTA
#define NTHREADS 256
#define NSTAGES 5   // per-warp cp.async A stages (1KB each)

// dynamic smem layout (bytes)
#define SB_OFF    0                       // B tile fp16: 32KB
#define SA_OFF    32768                   // A ring: 8 warps * 5 stages * 1KB = 40KB
#define SKERN_OFF 73728                   // 64 floats
#define SBIAS_OFF 73984                   // 64 floats
#define SMEM_TOTAL 74240

// fp16 copy of si_W with K-permuted columns (see phys_col), row n = k*16+a
__device__ __half g_Wh[NN * ND];

__device__ __forceinline__ unsigned pack_h2(float a, float b) {
    __half2 h = __floats2half2_rn(a, b);
    return *reinterpret_cast<unsigned*>(&h);
}

// Within each 16-wide K block: logical fragment col l -> physical col.
// logical {2q,2q+1}->phys{4q,4q+1}; logical {2q+8,2q+9}->phys{4q+2,4q+3}
__device__ __host__ __forceinline__ int phys_col(int l) {
    if (l < 8) return 4 * (l >> 1) + (l & 1);
    int lm = l - 8;
    return 4 * (lm >> 1) + 2 + (lm & 1);
}

#define CP_ASYNC_CG16(dst_u32, src_ptr) \
    asm volatile("cp.async.cg.shared.global [%0], [%1], 16;\n" :: "r"(dst_u32), "l"(src_ptr))
#define CP_COMMIT()  asm volatile("cp.async.commit_group;\n" ::: "memory")
#define CP_WAIT3()   asm volatile("cp.async.wait_group 3;\n" ::: "memory")

// ---------------------------------------------------------------------------
// Prep: convert si_W -> fp16 with K-permutation, write scalar tail outputs.
// ---------------------------------------------------------------------------
__global__ void prep_kernel(const float* __restrict__ siW,
                            const float* __restrict__ sel,
                            const float* __restrict__ keys,
                            float* __restrict__ out,
                            int Btot, int out_size)
{
    int i = blockIdx.x * blockDim.x + threadIdx.x;
    if (i < NN * ND) {
        int n = i >> 8, col = i & 255;
        int kk = col >> 4, l = col & 15;
        g_Wh[i] = __float2half_rn(siW[n * ND + kk * 16 + phys_col(l)]);
    }
    if (blockIdx.x == 0 && threadIdx.x == 0 && out_size >= Btot + 5) {
        float ssq = 0.f;
        for (int h = 0; h < 4; ++h) {
            float d = 0.f;
            for (int e = 0; e < 64; ++e) d = fmaf(sel[h * 64 + e], keys[h * 64 + e], d);
            ssq += d * d;
        }
        out[Btot] = 0.001f * ssq;                 // attend_mag_regs
        float aw = 0.0625f;                        // softmax of equal logits
        float ent = -16.0f * (logf(aw + 1e-8f) * aw);
        for (int h = 0; h < 4; ++h) out[Btot + 1 + h] = ent;  // head_entropies
    }
}

// ---------------------------------------------------------------------------
// Main: GEMM (M=Btot, K=256, N=64) fp16 mma.sync + fused epilogue.
//   A : per-warp 5-stage cp.async.cg ring (register-free MLP, no CTA barriers)
//   B : g_Wh -> smem, XOR-swizzled, ldmatrix
// ---------------------------------------------------------------------------
__global__ void __launch_bounds__(NTHREADS, 3)
mixer_kernel(const float* __restrict__ aq,
             const float* __restrict__ acts,
             const float* __restrict__ mq,
             const float* __restrict__ Vp,
             const float* __restrict__ si_keys,
             const float* __restrict__ si_agents,
             const float* __restrict__ si_b,
             float* __restrict__ out,
             int Btot)
{
    extern __shared__ char smem[];
    __half* sB    = reinterpret_cast<__half*>(smem + SB_OFF);
    float4* sA4   = reinterpret_cast<float4*>(smem + SA_OFF);
    float*  sKern = reinterpret_cast<float*>(smem + SKERN_OFF);
    float*  sBias = reinterpret_cast<float*>(smem + SBIAS_OFF);

    const int tid = threadIdx.x;

    if (tid < NN) {
        int k = tid >> 4;
        float sg = 1.0f / (1.0f + __expf(-si_agents[tid]));
        sKern[tid] = (fabsf(si_keys[k]) + 1e-10f) * sg;
        sBias[tid] = si_b[tid];
    }

    // stage B: 64 rows x 256 halves, 16B segments, seg' = seg ^ (row&7) swizzle
#pragma unroll
    for (int it = 0; it < 8; ++it) {
        int s = it * NTHREADS + tid;
        int r = s >> 5, c8 = s & 31;
        uint4 v = *reinterpret_cast<const uint4*>(g_Wh + r * ND + c8 * 8);
        *reinterpret_cast<uint4*>(sB + r * ND + ((c8 ^ (r & 7)) << 3)) = v;
    }
    __syncthreads();

    const int w = tid >> 5, l = tid & 31;
    const int quad = l >> 2, qid = l & 3;
    const int l7 = l & 7, t8 = l >> 3;
    const long warpRow0 = (long)blockIdx.x * MT + w * 16;

    long r0 = warpRow0 + quad;
    long r1 = r0 + 8;
    long r0c = (r0 < Btot) ? r0 : (long)(Btot - 1);
    long r1c = (r1 < Btot) ? r1 : (long)(Btot - 1);
    const int cA = qid * 2;

    // cp.async lane geometry: 2 segments/lane/stage; idx = l + 32*i
    const int ldRowA = l >> 2;            // row for segment 0
    const int ldC4A  = l & 3;
    long gRow0 = warpRow0 + ldRowA;       if (gRow0 >= Btot) gRow0 = Btot - 1;
    long gRow1 = warpRow0 + 8 + ldRowA;   if (gRow1 >= Btot) gRow1 = Btot - 1;
    const float* gA0 = acts + gRow0 * ND + ldC4A * 4;
    const float* gA1 = acts + gRow1 * ND + ldC4A * 4;

    const unsigned sAaddr = (unsigned)__cvta_generic_to_shared(sA4);
    const unsigned sBaddr = (unsigned)__cvta_generic_to_shared(sB);
    // per-(warp,stage) ring base in bytes; lane segment offsets
    const unsigned segOff0 = (unsigned)((ldRowA * 4 + ldC4A) * 16);
    const unsigned segOff1 = segOff0 + 8 * 4 * 16;

    // B ldmatrix lane geometry
    const int rowB_off = (t8 >> 1) * 8 + l7;
    const int s0B = t8 & 1;

    float acc[8][4];
#pragma unroll
    for (int i = 0; i < 8; ++i)
#pragma unroll
        for (int j = 0; j < 4; ++j) acc[i][j] = 0.f;

    // prologue: stages for k = 0,1,2
#pragma unroll
    for (int kk = 0; kk < 3; ++kk) {
        unsigned stBase = sAaddr + (unsigned)((w * NSTAGES + (kk % NSTAGES)) * 1024);
        CP_ASYNC_CG16(stBase + segOff0, gA0 + kk * 16);
        CP_ASYNC_CG16(stBase + segOff1, gA1 + kk * 16);
        CP_COMMIT();
    }

#pragma unroll
    for (int kk = 0; kk < 16; ++kk) {
        // issue stage kk+3 (buffer reused 2 iterations after its last read)
        if (kk + 3 < 16) {
            unsigned stBase = sAaddr + (unsigned)((w * NSTAGES + ((kk + 3) % NSTAGES)) * 1024);
            CP_ASYNC_CG16(stBase + segOff0, gA0 + (kk + 3) * 16);
            CP_ASYNC_CG16(stBase + segOff1, gA1 + (kk + 3) * 16);
        }
        CP_COMMIT();
        CP_WAIT3();           // stage kk complete
        __syncwarp();

        // consume stage kk%NSTAGES
        const float4* st = sA4 + (w * NSTAGES + (kk % NSTAGES)) * 64;
        float4 f0 = st[quad * 4 + qid];
        float4 f1 = st[(quad + 8) * 4 + qid];
        unsigned a0 = pack_h2(f0.x, f0.y);
        unsigned a1 = pack_h2(f1.x, f1.y);
        unsigned a2 = pack_h2(f0.z, f0.w);
        unsigned a3 = pack_h2(f1.z, f1.w);
#pragma unroll
        for (int p = 0; p < 4; ++p) {
            unsigned addrB = sBaddr
                           + (unsigned)((p * 16 + rowB_off) * (ND * 2))
                           + (unsigned)(((kk * 2 + s0B) ^ l7) << 4);
            unsigned b0, b1, b2, b3;
            asm volatile("ldmatrix.sync.aligned.m8n8.x4.shared.b16 {%0,%1,%2,%3}, [%4];\n"
                         : "=r"(b0), "=r"(b1), "=r"(b2), "=r"(b3) : "r"(addrB));
            asm volatile("mma.sync.aligned.m16n8k16.row.col.f32.f16.f16.f32 "
                         "{%0,%1,%2,%3}, {%4,%5,%6,%7}, {%8,%9}, {%0,%1,%2,%3};\n"
                         : "+f"(acc[2*p][0]), "+f"(acc[2*p][1]),
                           "+f"(acc[2*p][2]), "+f"(acc[2*p][3])
                         : "r"(a0), "r"(a1), "r"(a2), "r"(a3), "r"(b0), "r"(b1));
            asm volatile("mma.sync.aligned.m16n8k16.row.col.f32.f16.f16.f32 "
                         "{%0,%1,%2,%3}, {%4,%5,%6,%7}, {%8,%9}, {%0,%1,%2,%3};\n"
                         : "+f"(acc[2*p+1][0]), "+f"(acc[2*p+1][1]),
                           "+f"(acc[2*p+1][2]), "+f"(acc[2*p+1][3])
                         : "r"(a0), "r"(a1), "r"(a2), "r"(a3), "r"(b2), "r"(b3));
        }
        __syncwarp();
    }

    // Epilogue. acc[nt][h*2+j] = logit for row (r0 + h*8), col n = nt*8 + cA + j.
    const float v = Vp[0] * 0.0625f;
    float partial[2] = {0.f, 0.f};
#pragma unroll
    for (int h = 0; h < 2; ++h) {
        long gr = (h == 0) ? r0c : r1c;
        const float* aqr = aq + gr * NA;
        const float* mqr = mq + gr * NA;
#pragma unroll
        for (int j = 0; j < 2; ++j) {
#pragma unroll
            for (int pp = 0; pp < 2; ++pp) {
                float s = 0.f;
#pragma unroll
                for (int q = 0; q < 4; ++q) {
                    int nt = 2 * q + pp;
                    int n = nt * 8 + cA + j;
                    float x = acc[nt][h * 2 + j] + sBias[n];
                    x = 1.0f / (1.0f + __expf(-x));
                    s = fmaf(x, sKern[n], s);
                }
                int a = cA + j + 8 * pp;
                float advq = fmaf(0.25f, __ldcs(aqr + a), v)
                           - fmaf(0.25f, __ldcs(mqr + a), v);
                partial[h] += advq * (s - 1.0f);
            }
        }
    }
    partial[0] += __shfl_xor_sync(0xffffffffu, partial[0], 1);
    partial[0] += __shfl_xor_sync(0xffffffffu, partial[0], 2);
    partial[1] += __shfl_xor_sync(0xffffffffu, partial[1], 1);
    partial[1] += __shfl_xor_sync(0xffffffffu, partial[1], 2);
    if (qid == 0) {
        if (r0 < Btot) out[r0] = partial[0];
        if (r1 < Btot) out[r1] = partial[1];
    }
}

// ---------------------------------------------------------------------------
extern "C" void kernel_launch(void* const* d_in, const int* in_sizes, int n_in,
                              void* d_out, int out_size)
{
    const float* agent_qs  = (const float*)d_in[0];
    const float* actions   = (const float*)d_in[1];
    const float* max_q_i   = (const float*)d_in[2];
    const float* selectors = (const float*)d_in[3];
    const float* keys      = (const float*)d_in[4];
    const float* V         = (const float*)d_in[5];
    const float* si_keys   = (const float*)d_in[6];
    const float* si_agents = (const float*)d_in[7];
    const float* si_W      = (const float*)d_in[8];
    const float* si_b      = (const float*)d_in[9];
    float* out = (float*)d_out;

    int Btot = in_sizes[0] / NA;   // B0*T

    cudaFuncSetAttribute(mixer_kernel,
                         cudaFuncAttributeMaxDynamicSharedMemorySize, SMEM_TOTAL);

    prep_kernel<<<64, 256>>>(si_W, selectors, keys, out, Btot, out_size);

    int grid = (Btot + MT - 1) / MT;
    mixer_kernel<<<grid, NTHREADS, SMEM_TOTAL>>>(agent_qs, actions, max_q_i, V,
                                                 si_keys, si_agents, si_b, out, Btot);
}